// round 5
// baseline (speedup 1.0000x reference)
#include <cuda_runtime.h>
#include <cuda_bf16.h>

#define BS 131072
#define PLEN 10
#define NCH1 23   // K1 = 361 padded to 368 = 23 chunks of 16

// -------- pre-split weights: packed bf16 (2 per u32 along k), hi & lo parts.
// Within every aligned group of 8 u32 along k, indices are PERMUTED so that the
// (B0,B1) mma operand pair (orig u32 tg and tg+4) sits at adjacent slots 2*tg, 2*tg+1.
__device__ __align__(16) unsigned g_W1h[NCH1 * 256 * 8], g_W1l[NCH1 * 256 * 8]; // [kc][n][8]
__device__ __align__(16) unsigned g_W2h[4 * 128 * 32],   g_W2l[4 * 128 * 32];   // [kc][n][32]
__device__ __align__(16) unsigned g_W3h[64 * 64],        g_W3l[64 * 64];        // [n][64]
__device__ __align__(16) unsigned g_Whh[192 * 32],       g_Whl[192 * 32];       // [n][32]

// ---------------------------------------------------------------------------
__device__ __forceinline__ unsigned packbf(float lo, float hi) {
    unsigned r;
    asm("cvt.rn.bf16x2.f32 %0, %1, %2;" : "=r"(r) : "f"(hi), "f"(lo));
    return r;
}
// v0 -> low half, v1 -> high half; hi = bf16 round, lo = bf16(residual)
__device__ __forceinline__ void split2(float v0, float v1, unsigned& hi, unsigned& lo) {
    hi = packbf(v0, v1);
    float h0 = __uint_as_float(hi << 16);
    float h1 = __uint_as_float(hi & 0xffff0000u);
    lo = packbf(v0 - h0, v1 - h1);
}
__device__ __forceinline__ float bflo(unsigned u) { return __uint_as_float(u << 16); }
__device__ __forceinline__ float bfhi(unsigned u) { return __uint_as_float(u & 0xffff0000u); }
__device__ __forceinline__ float relu_(float v) { return v > 0.f ? v : 0.f; }

__device__ __forceinline__ void mma16(float* c, const unsigned* a, unsigned b0, unsigned b1) {
    asm("mma.sync.aligned.m16n8k16.row.col.f32.bf16.bf16.f32 "
        "{%0,%1,%2,%3},{%4,%5,%6,%7},{%8,%9},{%0,%1,%2,%3};"
        : "+f"(c[0]), "+f"(c[1]), "+f"(c[2]), "+f"(c[3])
        : "r"(a[0]), "r"(a[1]), "r"(a[2]), "r"(a[3]), "r"(b0), "r"(b1));
}

__device__ __forceinline__ void cpa4(void* s, const void* g) {
    unsigned a = (unsigned)__cvta_generic_to_shared(s);
    asm volatile("cp.async.ca.shared.global [%0],[%1],4;" :: "r"(a), "l"(g));
}
__device__ __forceinline__ void cpa16(void* s, const void* g) {
    unsigned a = (unsigned)__cvta_generic_to_shared(s);
    asm volatile("cp.async.cg.shared.global [%0],[%1],16;" :: "r"(a), "l"(g));
}
__device__ __forceinline__ void cp_commit() { asm volatile("cp.async.commit_group;"); }
template <int N>
__device__ __forceinline__ void cp_wait() { asm volatile("cp.async.wait_group %0;" :: "n"(N)); }

// load fp32 A tile fragment (16 rows) and split to bf16 hi/lo frags
__device__ __forceinline__ void ldA_f32(const float* base, int stride, int g, int tg,
                                        unsigned* Ah, unsigned* Al) {
    float2 p0 = *(const float2*)(base + g * stride + 2 * tg);
    float2 p1 = *(const float2*)(base + (g + 8) * stride + 2 * tg);
    float2 p2 = *(const float2*)(base + g * stride + 2 * tg + 8);
    float2 p3 = *(const float2*)(base + (g + 8) * stride + 2 * tg + 8);
    split2(p0.x, p0.y, Ah[0], Al[0]);
    split2(p1.x, p1.y, Ah[1], Al[1]);
    split2(p2.x, p2.y, Ah[2], Al[2]);
    split2(p3.x, p3.y, Ah[3], Al[3]);
}

// stored index s (within 8-group) -> original u32 index
__device__ __forceinline__ int inv_perm8(int s) {
    return (s & ~7) + ((s & 7) >> 1) + (s & 1) * 4;
}

// ---------------------------------------------------------------------------
// prep kernel: fp32 weights -> packed bf16 hi/lo global scratch (permuted pairs)
// ---------------------------------------------------------------------------
__global__ void prep_kernel(const float* __restrict__ W1, const float* __restrict__ W2,
                            const float* __restrict__ W3, const float* __restrict__ Whh) {
    int i = blockIdx.x * 256 + threadIdx.x;
    const int N1 = NCH1 * 256 * 8, N2 = 4 * 128 * 32, N3 = 64 * 64, N4 = 192 * 32;
    if (i < N1) {
        int kc = i >> 11, rem = i & 2047, n = rem >> 3, s = rem & 7;
        int u = inv_perm8(s);
        int k = kc * 16 + 2 * u;
        float v0 = (k < 361)     ? W1[n * 361 + k]     : 0.f;
        float v1 = (k + 1 < 361) ? W1[n * 361 + k + 1] : 0.f;
        split2(v0, v1, g_W1h[i], g_W1l[i]);
    } else if (i < N1 + N2) {
        int j = i - N1;
        int kc = j >> 12, rem = j & 4095, n = rem >> 5, s = rem & 31;
        int k = kc * 64 + 2 * inv_perm8(s);
        split2(W2[n * 256 + k], W2[n * 256 + k + 1], g_W2h[j], g_W2l[j]);
    } else if (i < N1 + N2 + N3) {
        int j = i - N1 - N2;
        int n = j >> 6, s = j & 63;
        int k = 2 * inv_perm8(s);
        split2(W3[n * 128 + k], W3[n * 128 + k + 1], g_W3h[j], g_W3l[j]);
    } else if (i < N1 + N2 + N3 + N4) {
        int j = i - N1 - N2 - N3;
        int n = j >> 5, s = j & 31;
        int k = 2 * inv_perm8(s);
        split2(Whh[n * 64 + k], Whh[n * 64 + k + 1], g_Whh[j], g_Whl[j]);
    }
}

// ---------------------------------------------------------------------------
// fused kernel: MLP (3 GEMMs) + GRU (10 steps), 128 rows per CTA, 1024 threads.
// Warp grid: wm = wid&7 (16 rows each), wn = wid>>3 (4 n-groups).
// smem (u32 units), peak 52224 = 208896 B:
//  h1_hi [128][132] @0, h1_lo @16896                                 (..33792)
//  P1: zbuf 2x[128][20] @33792, w1h 2x[256][12] @38912, w1l @45056   (..51200)
//  P2: w2h 2x[128][36] @33792, w2l @43008                            (..52224)
//  P3: w3h [64][68] @0, w3l @4352, h2hi [128][68] @33792, h2lo @42496
//  GRU: hhi [128][36] @0, hlo @4608, whhh [192][36] @9216, whhl @16128,
//       gh fp32 [128][196] @23040, wih @48128, bih @48512, bhh @48704,
//       wo @48896, bo @49024, x @49028, xh [128][20] @49284          (..51844)
// ---------------------------------------------------------------------------
__global__ void __launch_bounds__(1024, 1) fused_kernel(
    const float* __restrict__ z,
    const float* __restrict__ b1, const float* __restrict__ b2, const float* __restrict__ b3,
    const float* __restrict__ Wih, const float* __restrict__ bih, const float* __restrict__ bhh,
    const float* __restrict__ Wo, const float* __restrict__ bo,
    float* __restrict__ out)
{
    extern __shared__ float sm[];
    unsigned* smu = (unsigned*)sm;

    const int tid = threadIdx.x, lane = tid & 31, wid = tid >> 5;
    const int g = lane >> 2, tg = lane & 3;
    const int wm = wid & 7, wn = wid >> 3;
    const int m0 = blockIdx.x * 128;

    unsigned* h1hi = smu;            // [128][132]
    unsigned* h1lo = smu + 16896;
    float*    zbuf = sm + 33792;     // 2 x [128][20]
    unsigned* w1h  = smu + 38912;    // 2 x [256][12]
    unsigned* w1l  = smu + 45056;

    // ================= GEMM1: h1 = relu(z @ W1^T + b1) =================
    float acc1[8][4];
    #pragma unroll
    for (int b = 0; b < 8; b++)
        #pragma unroll
        for (int c = 0; c < 4; c++) acc1[b][c] = 0.f;

    auto stage1 = [&](int buf, int kc) {
        const int k0 = kc * 16;
        // z: 128 rows x 16 fp32 (row stride 361 not 16B-aligned -> 4B cp.async)
        #pragma unroll
        for (int i = tid; i < 2048; i += 1024) {
            int r = i >> 4, c = i & 15, k = k0 + c;
            float* dst = zbuf + buf * 2560 + r * 20 + c;
            if (k < 361) cpa4(dst, z + (size_t)(m0 + r) * 361 + k);
            else         *dst = 0.f;
        }
        // W1 chunk: 256 rows x 8 u32 (hi & lo), 1024 threads -> 1 vec4 each
        {
            int half = tid >> 9, t = tid & 511;
            int n = t >> 1, q4 = (t & 1) * 4;
            const unsigned* src = (half ? g_W1l : g_W1h) + kc * 2048 + n * 8 + q4;
            unsigned* dst = (half ? w1l : w1h) + buf * 3072 + n * 12 + q4;
            cpa16(dst, src);
        }
    };

    stage1(0, 0); cp_commit();
    for (int kc = 0; kc < NCH1; kc++) {
        if (kc + 1 < NCH1) { stage1((kc + 1) & 1, kc + 1); cp_commit(); cp_wait<1>(); }
        else               { cp_wait<0>(); }
        __syncthreads();
        const float* az = zbuf + (kc & 1) * 2560 + (wm * 16) * 20;
        const unsigned* bh = w1h + (kc & 1) * 3072;
        const unsigned* bl = w1l + (kc & 1) * 3072;
        unsigned Ah[4], Al[4];
        ldA_f32(az, 20, g, tg, Ah, Al);
        #pragma unroll
        for (int nt = 0; nt < 8; nt++) {
            int nrow = wn * 64 + nt * 8 + g;
            uint2 B = *(const uint2*)(bh + nrow * 12 + tg * 2);
            uint2 C = *(const uint2*)(bl + nrow * 12 + tg * 2);
            mma16(acc1[nt], Ah, B.x, B.y);
            mma16(acc1[nt], Ah, C.x, C.y);
            mma16(acc1[nt], Al, B.x, B.y);
        }
        __syncthreads();
    }

    // prefetch W2 chunk 0 (over dead z/W1 region)
    unsigned* w2h = smu + 33792;  // 2 x [128][36]
    unsigned* w2l = smu + 43008;
    auto stage2 = [&](int buf, int kc) {
        #pragma unroll
        for (int i = tid; i < 2048; i += 1024) {
            int half = i >> 10, j = i & 1023;
            int n = j >> 3, q4 = (j & 7) * 4;
            cpa16((half ? w2l : w2h) + buf * 4608 + n * 36 + q4,
                  (half ? g_W2l : g_W2h) + kc * 4096 + n * 32 + q4);
        }
    };
    stage2(0, 0); cp_commit();

    // GEMM1 epilogue: h1 = relu(acc + b1) -> packed bf16 hi/lo (natural layout)
    #pragma unroll
    for (int nt = 0; nt < 8; nt++) {
        int m = wm * 16 + g;
        int n = wn * 64 + nt * 8 + 2 * tg;
        int nu = n >> 1;
        float bv0 = __ldg(b1 + n), bv1 = __ldg(b1 + n + 1);
        unsigned hi, lo;
        split2(relu_(acc1[nt][0] + bv0), relu_(acc1[nt][1] + bv1), hi, lo);
        h1hi[m * 132 + nu] = hi; h1lo[m * 132 + nu] = lo;
        split2(relu_(acc1[nt][2] + bv0), relu_(acc1[nt][3] + bv1), hi, lo);
        h1hi[(m + 8) * 132 + nu] = hi; h1lo[(m + 8) * 132 + nu] = lo;
    }
    __syncthreads();

    // ================= GEMM2: h2 = relu(h1 @ W2^T + b2) =================
    float acc2[4][4];
    #pragma unroll
    for (int b = 0; b < 4; b++)
        #pragma unroll
        for (int c = 0; c < 4; c++) acc2[b][c] = 0.f;

    for (int kc = 0; kc < 4; kc++) {
        if (kc + 1 < 4) { stage2((kc + 1) & 1, kc + 1); cp_commit(); cp_wait<1>(); }
        else            { cp_wait<0>(); }
        __syncthreads();
        const unsigned* bh = w2h + (kc & 1) * 4608;
        const unsigned* bl = w2l + (kc & 1) * 4608;
        #pragma unroll
        for (int q = 0; q < 4; q++) {
            int u0 = kc * 32 + q * 8;
            int m = wm * 16 + g;
            unsigned Ah[4], Al[4];
            Ah[0] = h1hi[m * 132 + u0 + tg];       Ah[1] = h1hi[(m + 8) * 132 + u0 + tg];
            Ah[2] = h1hi[m * 132 + u0 + tg + 4];   Ah[3] = h1hi[(m + 8) * 132 + u0 + tg + 4];
            Al[0] = h1lo[m * 132 + u0 + tg];       Al[1] = h1lo[(m + 8) * 132 + u0 + tg];
            Al[2] = h1lo[m * 132 + u0 + tg + 4];   Al[3] = h1lo[(m + 8) * 132 + u0 + tg + 4];
            #pragma unroll
            for (int nt = 0; nt < 4; nt++) {
                int nrow = wn * 32 + nt * 8 + g;
                uint2 B = *(const uint2*)(bh + nrow * 36 + q * 8 + tg * 2);
                uint2 C = *(const uint2*)(bl + nrow * 36 + q * 8 + tg * 2);
                mma16(acc2[nt], Ah, B.x, B.y);
                mma16(acc2[nt], Ah, C.x, C.y);
                mma16(acc2[nt], Al, B.x, B.y);
            }
        }
        __syncthreads();
    }

    // stage W3 (over dead h1 region @0) while writing h2 epilogue
    unsigned* w3h = smu;          // [64][68]
    unsigned* w3l = smu + 4352;
    #pragma unroll
    for (int i = tid; i < 2048; i += 1024) {
        int half = i >> 10, j = i & 1023;
        int n = j >> 4, q4 = (j & 15) * 4;
        cpa16((half ? w3l : w3h) + n * 68 + q4, (half ? g_W3l : g_W3h) + n * 64 + q4);
    }
    cp_commit();

    unsigned* h2hi = smu + 33792;  // [128][68] (over dead W2 bufs)
    unsigned* h2lo = smu + 42496;
    #pragma unroll
    for (int nt = 0; nt < 4; nt++) {
        int m = wm * 16 + g;
        int n = wn * 32 + nt * 8 + 2 * tg;
        int nu = n >> 1;
        float bv0 = __ldg(b2 + n), bv1 = __ldg(b2 + n + 1);
        unsigned hi, lo;
        split2(relu_(acc2[nt][0] + bv0), relu_(acc2[nt][1] + bv1), hi, lo);
        h2hi[m * 68 + nu] = hi; h2lo[m * 68 + nu] = lo;
        split2(relu_(acc2[nt][2] + bv0), relu_(acc2[nt][3] + bv1), hi, lo);
        h2hi[(m + 8) * 68 + nu] = hi; h2lo[(m + 8) * 68 + nu] = lo;
    }
    cp_wait<0>();
    __syncthreads();

    // ================= GEMM3: h = relu(h2 @ W3^T + b3) =================
    float acc3[2][4];
    #pragma unroll
    for (int b = 0; b < 2; b++)
        #pragma unroll
        for (int c = 0; c < 4; c++) acc3[b][c] = 0.f;

    #pragma unroll
    for (int q = 0; q < 8; q++) {
        int u0 = q * 8;
        int m = wm * 16 + g;
        unsigned Ah[4], Al[4];
        Ah[0] = h2hi[m * 68 + u0 + tg];       Ah[1] = h2hi[(m + 8) * 68 + u0 + tg];
        Ah[2] = h2hi[m * 68 + u0 + tg + 4];   Ah[3] = h2hi[(m + 8) * 68 + u0 + tg + 4];
        Al[0] = h2lo[m * 68 + u0 + tg];       Al[1] = h2lo[(m + 8) * 68 + u0 + tg];
        Al[2] = h2lo[m * 68 + u0 + tg + 4];   Al[3] = h2lo[(m + 8) * 68 + u0 + tg + 4];
        #pragma unroll
        for (int nt = 0; nt < 2; nt++) {
            int nrow = wn * 16 + nt * 8 + g;
            uint2 B = *(const uint2*)(w3h + nrow * 68 + q * 8 + tg * 2);
            uint2 C = *(const uint2*)(w3l + nrow * 68 + q * 8 + tg * 2);
            mma16(acc3[nt], Ah, B.x, B.y);
            mma16(acc3[nt], Ah, C.x, C.y);
            mma16(acc3[nt], Al, B.x, B.y);
        }
    }
    __syncthreads();   // all reads of h2/w3 complete before overwrite

    // ================= GRU setup =================
    unsigned* hhi  = smu;            // [128][36]
    unsigned* hlo  = smu + 4608;
    unsigned* whhh = smu + 9216;     // [192][36]
    unsigned* whhl = smu + 16128;
    float*    gh   = sm + 23040;     // [128][196]
    float*    wih  = sm + 48128;     // [192][2]
    float*    sbih = sm + 48512;
    float*    sbhh = sm + 48704;
    float*    swo  = sm + 48896;
    float*    sbo  = sm + 49024;
    float*    x    = sm + 49028;     // [128][2]
    float*    xh   = sm + 49284;     // [128][20]

    // stage Whh + small arrays (regions dead after the sync above)
    #pragma unroll
    for (int i = tid; i < 3072; i += 1024) {
        int half = (i >= 1536), j = half ? i - 1536 : i;
        int n = j >> 3, q4 = (j & 7) * 4;
        cpa16((half ? whhl : whhh) + n * 36 + q4, (half ? g_Whl : g_Whh) + n * 32 + q4);
    }
    cp_commit();
    if (tid < 384) wih[tid] = Wih[tid];
    if (tid < 192) { sbih[tid] = bih[tid]; sbhh[tid] = bhh[tid]; }
    if (tid < 128) swo[tid] = Wo[tid];
    if (tid < 2)   sbo[tid] = bo[tid];
    if (tid < 256) x[tid] = 0.f;

    // GEMM3 epilogue: h = relu(acc + b3) -> packed bf16 hi/lo
    #pragma unroll
    for (int nt = 0; nt < 2; nt++) {
        int m = wm * 16 + g;
        int n = wn * 16 + nt * 8 + 2 * tg;
        int nu = n >> 1;
        float bv0 = __ldg(b3 + n), bv1 = __ldg(b3 + n + 1);
        unsigned hi, lo;
        split2(relu_(acc3[nt][0] + bv0), relu_(acc3[nt][1] + bv1), hi, lo);
        hhi[m * 36 + nu] = hi; hlo[m * 36 + nu] = lo;
        split2(relu_(acc3[nt][2] + bv0), relu_(acc3[nt][3] + bv1), hi, lo);
        hhi[(m + 8) * 36 + nu] = hi; hlo[(m + 8) * 36 + nu] = lo;
    }
    cp_wait<0>();
    __syncthreads();

    // ================= GRU loop =================
    const int gr = tid >> 3;           // gate row
    const int gc0 = (tid & 7) * 4;     // gate u32 col base
    for (int t = 0; t < PLEN; t++) {
        // ---- gh = h @ Whh^T ----
        float acc[6][4];
        #pragma unroll
        for (int b = 0; b < 6; b++)
            #pragma unroll
            for (int c = 0; c < 4; c++) acc[b][c] = 0.f;

        #pragma unroll
        for (int q = 0; q < 4; q++) {
            int u0 = q * 8;
            int m = wm * 16 + g;
            unsigned Ah[4], Al[4];
            Ah[0] = hhi[m * 36 + u0 + tg];       Ah[1] = hhi[(m + 8) * 36 + u0 + tg];
            Ah[2] = hhi[m * 36 + u0 + tg + 4];   Ah[3] = hhi[(m + 8) * 36 + u0 + tg + 4];
            Al[0] = hlo[m * 36 + u0 + tg];       Al[1] = hlo[(m + 8) * 36 + u0 + tg];
            Al[2] = hlo[m * 36 + u0 + tg + 4];   Al[3] = hlo[(m + 8) * 36 + u0 + tg + 4];
            #pragma unroll
            for (int nt = 0; nt < 6; nt++) {
                int nrow = wn * 48 + nt * 8 + g;
                uint2 B = *(const uint2*)(whhh + nrow * 36 + q * 8 + tg * 2);
                uint2 C = *(const uint2*)(whhl + nrow * 36 + q * 8 + tg * 2);
                mma16(acc[nt], Ah, B.x, B.y);
                mma16(acc[nt], Ah, C.x, C.y);
                mma16(acc[nt], Al, B.x, B.y);
            }
        }
        #pragma unroll
        for (int nt = 0; nt < 6; nt++) {
            int m = wm * 16 + g;
            int n = wn * 48 + nt * 8 + 2 * tg;
            *(float2*)&gh[m * 196 + n]       = make_float2(acc[nt][0], acc[nt][1]);
            *(float2*)&gh[(m + 8) * 196 + n] = make_float2(acc[nt][2], acc[nt][3]);
        }
        __syncthreads();

        // ---- gates (exact fp32), h update in packed hi/lo ----
        {
            float x0v = x[gr * 2], x1v = x[gr * 2 + 1];
            #pragma unroll
            for (int i = 0; i < 4; i++) {
                int c = gc0 + i;
                unsigned uh = hhi[gr * 36 + c], ul = hlo[gr * 36 + c];
                float hv0 = bflo(uh) + bflo(ul);
                float hv1 = bfhi(uh) + bfhi(ul);
                float hn[2];
                #pragma unroll
                for (int e = 0; e < 2; e++) {
                    int j = 2 * c + e;
                    float ghr = gh[gr * 196 + j]       + sbhh[j];
                    float ghz = gh[gr * 196 + j + 64]  + sbhh[j + 64];
                    float ghn = gh[gr * 196 + j + 128] + sbhh[j + 128];
                    float gir = x0v * wih[j * 2]           + x1v * wih[j * 2 + 1]           + sbih[j];
                    float giz = x0v * wih[(j + 64) * 2]    + x1v * wih[(j + 64) * 2 + 1]    + sbih[j + 64];
                    float gin = x0v * wih[(j + 128) * 2]   + x1v * wih[(j + 128) * 2 + 1]   + sbih[j + 128];
                    float rg = __fdividef(1.f, 1.f + __expf(-(gir + ghr)));
                    float zg = __fdividef(1.f, 1.f + __expf(-(giz + ghz)));
                    float av = gin + rg * ghn;
                    float e2 = __expf(2.f * fabsf(av));
                    float tv = 1.f - __fdividef(2.f, e2 + 1.f);
                    float ng = copysignf(tv, av);
                    float hv = e ? hv1 : hv0;
                    hn[e] = (1.f - zg) * ng + zg * hv;
                }
                unsigned nhi, nlo;
                split2(hn[0], hn[1], nhi, nlo);
                hhi[gr * 36 + c] = nhi; hlo[gr * 36 + c] = nlo;
            }
        }
        __syncthreads();

        // ---- dx = h_new @ Wo^T + bo ; x += dx (no trailing sync: covered next iter) ----
        if (tid < 256) {
            int r = tid >> 1, o = tid & 1;
            float s = sbo[o];
            const float* wr = swo + o * 64;
            #pragma unroll 8
            for (int c = 0; c < 32; c++) {
                unsigned uh = hhi[r * 36 + c], ul = hlo[r * 36 + c];
                s += (bflo(uh) + bflo(ul)) * wr[2 * c];
                s += (bfhi(uh) + bfhi(ul)) * wr[2 * c + 1];
            }
            float xv = x[r * 2 + o] + s;
            x[r * 2 + o] = xv;
            xh[r * 20 + t * 2 + o] = xv;
        }
    }
    __syncthreads();

    // coalesced output: out[b, t, o]
    if (tid < 640) {
        int r = tid / 5, q = (tid % 5) * 4;
        *(float4*)&out[(size_t)(m0 + r) * 20 + q] = *(const float4*)&xh[r * 20 + q];
    }
}

// ---------------------------------------------------------------------------
extern "C" void kernel_launch(void* const* d_in, const int* in_sizes, int n_in,
                              void* d_out, int out_size)
{
    const float* z   = (const float*)d_in[0];
    const float* W1  = (const float*)d_in[1];
    const float* b1  = (const float*)d_in[2];
    const float* W2  = (const float*)d_in[3];
    const float* b2  = (const float*)d_in[4];
    const float* W3  = (const float*)d_in[5];
    const float* b3  = (const float*)d_in[6];
    const float* Wih = (const float*)d_in[7];
    const float* Whh = (const float*)d_in[8];
    const float* bih = (const float*)d_in[9];
    const float* bhh = (const float*)d_in[10];
    const float* Wo  = (const float*)d_in[11];
    const float* bo  = (const float*)d_in[12];
    float* out = (float*)d_out;

    const int smem = 52224 * 4;  // 208896 B
    cudaFuncSetAttribute(fused_kernel, cudaFuncAttributeMaxDynamicSharedMemorySize, smem);

    prep_kernel<<<288, 256>>>(W1, W2, W3, Whh);
    fused_kernel<<<BS / 128, 1024, smem>>>(z, b1, b2, b3, Wih, bih, bhh, Wo, bo, out);
}

// round 8
// speedup vs baseline: 1.2067x; 1.2067x over previous
#include <cuda_runtime.h>
#include <cuda_bf16.h>

#define BS 131072
#define PLEN 10
#define NCH1 23   // GEMM1: K=361 padded to 368 = 23 chunks of 16

// -------- pre-split weights: packed bf16 (2 per u32 along k), hi & lo parts.
// Within every aligned group of 8 u32 along k, indices are PERMUTED so the
// (B0,B1) mma operand pair (orig u32 tg, tg+4) sits at adjacent slots 2tg, 2tg+1.
__device__ __align__(16) unsigned g_W1h[NCH1 * 256 * 8], g_W1l[NCH1 * 256 * 8]; // [kc][n][8]
__device__ __align__(16) unsigned g_W2h[8 * 128 * 16],   g_W2l[8 * 128 * 16];   // [kc][n][16]
__device__ __align__(16) unsigned g_W3h[64 * 64],        g_W3l[64 * 64];        // [n][64]
__device__ __align__(16) unsigned g_Whh[192 * 32],       g_Whl[192 * 32];       // [n][32]

// ---------------------------------------------------------------------------
__device__ __forceinline__ unsigned packbf(float lo, float hi) {
    unsigned r;
    asm("cvt.rn.bf16x2.f32 %0, %1, %2;" : "=r"(r) : "f"(hi), "f"(lo));
    return r;
}
__device__ __forceinline__ void split2(float v0, float v1, unsigned& hi, unsigned& lo) {
    hi = packbf(v0, v1);
    float h0 = __uint_as_float(hi << 16);
    float h1 = __uint_as_float(hi & 0xffff0000u);
    lo = packbf(v0 - h0, v1 - h1);
}
__device__ __forceinline__ float bflo(unsigned u) { return __uint_as_float(u << 16); }
__device__ __forceinline__ float bfhi(unsigned u) { return __uint_as_float(u & 0xffff0000u); }
__device__ __forceinline__ float relu_(float v) { return v > 0.f ? v : 0.f; }

__device__ __forceinline__ void mma16(float* c, const unsigned* a, unsigned b0, unsigned b1) {
    asm("mma.sync.aligned.m16n8k16.row.col.f32.bf16.bf16.f32 "
        "{%0,%1,%2,%3},{%4,%5,%6,%7},{%8,%9},{%0,%1,%2,%3};"
        : "+f"(c[0]), "+f"(c[1]), "+f"(c[2]), "+f"(c[3])
        : "r"(a[0]), "r"(a[1]), "r"(a[2]), "r"(a[3]), "r"(b0), "r"(b1));
}

__device__ __forceinline__ void cpa4(void* s, const void* g) {
    unsigned a = (unsigned)__cvta_generic_to_shared(s);
    asm volatile("cp.async.ca.shared.global [%0],[%1],4;" :: "r"(a), "l"(g) : "memory");
}
__device__ __forceinline__ void cpa16(void* s, const void* g) {
    unsigned a = (unsigned)__cvta_generic_to_shared(s);
    asm volatile("cp.async.cg.shared.global [%0],[%1],16;" :: "r"(a), "l"(g) : "memory");
}
__device__ __forceinline__ void cp_commit() { asm volatile("cp.async.commit_group;" ::: "memory"); }
template <int N>
__device__ __forceinline__ void cp_wait() { asm volatile("cp.async.wait_group %0;" :: "n"(N) : "memory"); }

__device__ __forceinline__ void bar_sync(int id)   { asm volatile("bar.sync %0, 512;"   :: "r"(id) : "memory"); }
__device__ __forceinline__ void bar_arrive(int id) { asm volatile("bar.arrive %0, 512;" :: "r"(id) : "memory"); }

// load fp32 A tile fragment (16 rows) and split to bf16 hi/lo frags
__device__ __forceinline__ void ldA_f32(const float* base, int stride, int g, int tg,
                                        unsigned* Ah, unsigned* Al) {
    float2 p0 = *(const float2*)(base + g * stride + 2 * tg);
    float2 p1 = *(const float2*)(base + (g + 8) * stride + 2 * tg);
    float2 p2 = *(const float2*)(base + g * stride + 2 * tg + 8);
    float2 p3 = *(const float2*)(base + (g + 8) * stride + 2 * tg + 8);
    split2(p0.x, p0.y, Ah[0], Al[0]);
    split2(p1.x, p1.y, Ah[1], Al[1]);
    split2(p2.x, p2.y, Ah[2], Al[2]);
    split2(p3.x, p3.y, Ah[3], Al[3]);
}

// stored index s (within 8-group) -> original u32 index
__device__ __forceinline__ int inv_perm8(int s) {
    return (s & ~7) + ((s & 7) >> 1) + (s & 1) * 4;
}

// ---------------------------------------------------------------------------
// prep kernel: fp32 weights -> packed bf16 hi/lo global scratch (permuted pairs)
// total elems = 47104 + 16384 + 4096 + 6144 = 73728 = 288 * 256
// ---------------------------------------------------------------------------
__global__ void prep_kernel(const float* __restrict__ W1, const float* __restrict__ W2,
                            const float* __restrict__ W3, const float* __restrict__ Whh) {
    int i = blockIdx.x * 256 + threadIdx.x;
    const int N1 = NCH1 * 256 * 8, N2 = 8 * 128 * 16, N3 = 64 * 64, N4 = 192 * 32;
    if (i < N1) {
        int kc = i >> 11, rem = i & 2047, n = rem >> 3, s = rem & 7;
        int k = kc * 16 + 2 * inv_perm8(s);
        float v0 = (k < 361)     ? W1[n * 361 + k]     : 0.f;
        float v1 = (k + 1 < 361) ? W1[n * 361 + k + 1] : 0.f;
        split2(v0, v1, g_W1h[i], g_W1l[i]);
    } else if (i < N1 + N2) {
        int j = i - N1;
        int kc = j >> 11, rem = j & 2047, n = rem >> 4, s = rem & 15;
        int k = kc * 32 + 2 * inv_perm8(s);
        split2(W2[n * 256 + k], W2[n * 256 + k + 1], g_W2h[j], g_W2l[j]);
    } else if (i < N1 + N2 + N3) {
        int j = i - N1 - N2;
        int n = j >> 6, s = j & 63;
        int k = 2 * inv_perm8(s);
        split2(W3[n * 128 + k], W3[n * 128 + k + 1], g_W3h[j], g_W3l[j]);
    } else if (i < N1 + N2 + N3 + N4) {
        int j = i - N1 - N2 - N3;
        int n = j >> 5, s = j & 31;
        int k = 2 * inv_perm8(s);
        split2(Whh[n * 64 + k], Whh[n * 64 + k + 1], g_Whh[j], g_Whl[j]);
    }
}

// ---------------------------------------------------------------------------
// fused kernel: MLP (3 GEMMs) + warp-specialized GRU. 128 rows/CTA, 512 thr.
// smem (u32 units), peak 54272 = 217088 B:
//  h1hi [128][132] @0, h1lo @16896                                  (..33792)
//  P1: zbuf 2x[128][24] @33792, w1h 2x[256][8] @39936, w1l @44032   (..48128)
//  P2: w2h 2x[128][40] @33792, w2l @44032                           (..54272)
//  P3: w3h [64][72] @0, w3l @4608;
//      h2hi [128][72] @16896, h2lo @26112   (rows are 64 u32 -> stride 72!)
//  GRU: hhi [128][36] @0, hlo @4608, whhh [192][40] @9216, whhl @16896,
//       gh fp32 [128][196] @24576, wih @49664, bih @50048, bhh @50240,
//       swo @50432, sbo @50560, x @50564, xh [128][20] @50820       (..53380)
// ---------------------------------------------------------------------------
__global__ void __launch_bounds__(512, 1) fused_kernel(
    const float* __restrict__ z,
    const float* __restrict__ b1, const float* __restrict__ b2, const float* __restrict__ b3,
    const float* __restrict__ Wih, const float* __restrict__ bih, const float* __restrict__ bhh,
    const float* __restrict__ Wo, const float* __restrict__ bo,
    float* __restrict__ out)
{
    extern __shared__ float sm[];
    unsigned* smu = (unsigned*)sm;

    const int tid = threadIdx.x, lane = tid & 31, wid = tid >> 5;
    const int g = lane >> 2, tg = lane & 3;
    const int wm = wid & 3, wn = wid >> 2;
    const int m0 = blockIdx.x * 128;

    unsigned* h1hi = smu;            // [128][132]
    unsigned* h1lo = smu + 16896;
    float*    zbuf = sm + 33792;     // 2 x [128][24]
    unsigned* w1h  = smu + 39936;    // 2 x [256][8]
    unsigned* w1l  = smu + 44032;

    // ================= GEMM1: h1 = relu(z @ W1^T + b1) =================
    float acc1[2][8][4];
    #pragma unroll
    for (int a = 0; a < 2; a++)
        #pragma unroll
        for (int b = 0; b < 8; b++)
            #pragma unroll
            for (int c = 0; c < 4; c++) acc1[a][b][c] = 0.f;

    auto stage1 = [&](int buf, int kc) {
        const int k0 = kc * 16;
        #pragma unroll
        for (int i = tid; i < 2048; i += 512) {
            int r = i >> 4, c = i & 15, k = k0 + c;
            float* dst = zbuf + buf * 3072 + r * 24 + c;
            if (k < 361) cpa4(dst, z + (size_t)(m0 + r) * 361 + k);
            else         *dst = 0.f;
        }
        #pragma unroll
        for (int i = tid; i < 1024; i += 512) {
            int half = i >> 9, j = i & 511;
            int n = j >> 1, q4 = (j & 1) * 4;
            cpa16((half ? w1l : w1h) + buf * 2048 + n * 8 + q4,
                  (half ? g_W1l : g_W1h) + kc * 2048 + n * 8 + q4);
        }
    };

    stage1(0, 0); cp_commit();
    for (int kc = 0; kc < NCH1; kc++) {
        cp_wait<0>();
        __syncthreads();                 // data kc ready; buffer (kc+1)&1 free
        if (kc + 1 < NCH1) { stage1((kc + 1) & 1, kc + 1); cp_commit(); }
        const float* az = zbuf + (kc & 1) * 3072 + (wm * 32) * 24;
        const unsigned* bh = w1h + (kc & 1) * 2048;
        const unsigned* bl = w1l + (kc & 1) * 2048;
        unsigned Ah[2][4], Al[2][4];
        ldA_f32(az,           24, g, tg, Ah[0], Al[0]);
        ldA_f32(az + 16 * 24, 24, g, tg, Ah[1], Al[1]);
        #pragma unroll
        for (int nt = 0; nt < 8; nt++) {
            int nrow = wn * 64 + nt * 8 + g;
            uint2 B = *(const uint2*)(bh + nrow * 8 + tg * 2);
            uint2 C = *(const uint2*)(bl + nrow * 8 + tg * 2);
            mma16(acc1[0][nt], Ah[0], B.x, B.y);
            mma16(acc1[1][nt], Ah[1], B.x, B.y);
            mma16(acc1[0][nt], Ah[0], C.x, C.y);
            mma16(acc1[1][nt], Ah[1], C.x, C.y);
            mma16(acc1[0][nt], Al[0], B.x, B.y);
            mma16(acc1[1][nt], Al[1], B.x, B.y);
        }
    }
    __syncthreads();   // all GEMM1 smem reads done before w2 overwrites region

    // ================= GEMM2 staging + h1 epilogue =================
    unsigned* w2h = smu + 33792;  // 2 x [128][40]
    unsigned* w2l = smu + 44032;
    auto stage2 = [&](int buf, int kc) {
        #pragma unroll
        for (int i = tid; i < 1024; i += 512) {
            int half = i >> 9, j = i & 511;
            int n = j >> 2, q4 = (j & 3) * 4;
            cpa16((half ? w2l : w2h) + buf * 5120 + n * 40 + q4,
                  (half ? g_W2l : g_W2h) + kc * 2048 + n * 16 + q4);
        }
    };
    stage2(0, 0); cp_commit();

    #pragma unroll
    for (int mt = 0; mt < 2; mt++) {
        #pragma unroll
        for (int nt = 0; nt < 8; nt++) {
            int m = wm * 32 + mt * 16 + g;
            int n = wn * 64 + nt * 8 + 2 * tg;
            int nu = n >> 1;
            float bv0 = __ldg(b1 + n), bv1 = __ldg(b1 + n + 1);
            unsigned hi, lo;
            split2(relu_(acc1[mt][nt][0] + bv0), relu_(acc1[mt][nt][1] + bv1), hi, lo);
            h1hi[m * 132 + nu] = hi; h1lo[m * 132 + nu] = lo;
            split2(relu_(acc1[mt][nt][2] + bv0), relu_(acc1[mt][nt][3] + bv1), hi, lo);
            h1hi[(m + 8) * 132 + nu] = hi; h1lo[(m + 8) * 132 + nu] = lo;
        }
    }

    // ================= GEMM2: h2 = relu(h1 @ W2^T + b2), 8 chunks of 32 ======
    float acc2[2][4][4];
    #pragma unroll
    for (int a = 0; a < 2; a++)
        #pragma unroll
        for (int b = 0; b < 4; b++)
            #pragma unroll
            for (int c = 0; c < 4; c++) acc2[a][b][c] = 0.f;

    for (int kc = 0; kc < 8; kc++) {
        cp_wait<0>();
        __syncthreads();
        if (kc + 1 < 8) { stage2((kc + 1) & 1, kc + 1); cp_commit(); }
        const unsigned* bh = w2h + (kc & 1) * 5120;
        const unsigned* bl = w2l + (kc & 1) * 5120;
        #pragma unroll
        for (int q = 0; q < 2; q++) {
            int u0 = kc * 16 + q * 8;
            unsigned Ah[2][4], Al[2][4];
            #pragma unroll
            for (int mt = 0; mt < 2; mt++) {
                int m = wm * 32 + mt * 16 + g;
                Ah[mt][0] = h1hi[m * 132 + u0 + tg];     Ah[mt][1] = h1hi[(m + 8) * 132 + u0 + tg];
                Ah[mt][2] = h1hi[m * 132 + u0 + tg + 4]; Ah[mt][3] = h1hi[(m + 8) * 132 + u0 + tg + 4];
                Al[mt][0] = h1lo[m * 132 + u0 + tg];     Al[mt][1] = h1lo[(m + 8) * 132 + u0 + tg];
                Al[mt][2] = h1lo[m * 132 + u0 + tg + 4]; Al[mt][3] = h1lo[(m + 8) * 132 + u0 + tg + 4];
            }
            #pragma unroll
            for (int nt = 0; nt < 4; nt++) {
                int nrow = wn * 32 + nt * 8 + g;
                uint2 B = *(const uint2*)(bh + nrow * 40 + q * 8 + tg * 2);
                uint2 C = *(const uint2*)(bl + nrow * 40 + q * 8 + tg * 2);
                mma16(acc2[0][nt], Ah[0], B.x, B.y);
                mma16(acc2[1][nt], Ah[1], B.x, B.y);
                mma16(acc2[0][nt], Ah[0], C.x, C.y);
                mma16(acc2[1][nt], Ah[1], C.x, C.y);
                mma16(acc2[0][nt], Al[0], B.x, B.y);
                mma16(acc2[1][nt], Al[1], B.x, B.y);
            }
        }
    }
    __syncthreads();   // all GEMM2 reads (h1 + w2) done

    // ---- stage W3 (over dead h1 head) + h2 epilogue ----
    unsigned* w3h = smu;          // [64][72]
    unsigned* w3l = smu + 4608;
    #pragma unroll
    for (int i = tid; i < 2048; i += 512) {
        int half = i >> 10, j = i & 1023;
        int n = j >> 4, q4 = (j & 15) * 4;
        cpa16((half ? w3l : w3h) + n * 72 + q4, (half ? g_W3l : g_W3h) + n * 64 + q4);
    }
    cp_commit();

    // h2 rows are 64 u32 -> stride 72 (the R6/R7 bug was stride 36 here)
    unsigned* h2hi = smu + 16896;  // [128][72] (dead h1lo / w2 regions)
    unsigned* h2lo = smu + 26112;
    #pragma unroll
    for (int mt = 0; mt < 2; mt++) {
        #pragma unroll
        for (int nt = 0; nt < 4; nt++) {
            int m = wm * 32 + mt * 16 + g;
            int n = wn * 32 + nt * 8 + 2 * tg;
            int nu = n >> 1;
            float bv0 = __ldg(b2 + n), bv1 = __ldg(b2 + n + 1);
            unsigned hi, lo;
            split2(relu_(acc2[mt][nt][0] + bv0), relu_(acc2[mt][nt][1] + bv1), hi, lo);
            h2hi[m * 72 + nu] = hi; h2lo[m * 72 + nu] = lo;
            split2(relu_(acc2[mt][nt][2] + bv0), relu_(acc2[mt][nt][3] + bv1), hi, lo);
            h2hi[(m + 8) * 72 + nu] = hi; h2lo[(m + 8) * 72 + nu] = lo;
        }
    }
    cp_wait<0>();
    __syncthreads();

    // ================= GEMM3: h = relu(h2 @ W3^T + b3) =================
    float acc3[2][2][4];
    #pragma unroll
    for (int a = 0; a < 2; a++)
        #pragma unroll
        for (int b = 0; b < 2; b++)
            #pragma unroll
            for (int c = 0; c < 4; c++) acc3[a][b][c] = 0.f;

    #pragma unroll
    for (int q = 0; q < 8; q++) {
        int u0 = q * 8;
        unsigned Ah[2][4], Al[2][4];
        #pragma unroll
        for (int mt = 0; mt < 2; mt++) {
            int m = wm * 32 + mt * 16 + g;
            Ah[mt][0] = h2hi[m * 72 + u0 + tg];     Ah[mt][1] = h2hi[(m + 8) * 72 + u0 + tg];
            Ah[mt][2] = h2hi[m * 72 + u0 + tg + 4]; Ah[mt][3] = h2hi[(m + 8) * 72 + u0 + tg + 4];
            Al[mt][0] = h2lo[m * 72 + u0 + tg];     Al[mt][1] = h2lo[(m + 8) * 72 + u0 + tg];
            Al[mt][2] = h2lo[m * 72 + u0 + tg + 4]; Al[mt][3] = h2lo[(m + 8) * 72 + u0 + tg + 4];
        }
        #pragma unroll
        for (int nt = 0; nt < 2; nt++) {
            int nrow = wn * 16 + nt * 8 + g;
            uint2 B = *(const uint2*)(w3h + nrow * 72 + q * 8 + tg * 2);
            uint2 C = *(const uint2*)(w3l + nrow * 72 + q * 8 + tg * 2);
            mma16(acc3[0][nt], Ah[0], B.x, B.y);
            mma16(acc3[1][nt], Ah[1], B.x, B.y);
            mma16(acc3[0][nt], Ah[0], C.x, C.y);
            mma16(acc3[1][nt], Ah[1], C.x, C.y);
            mma16(acc3[0][nt], Al[0], B.x, B.y);
            mma16(acc3[1][nt], Al[1], B.x, B.y);
        }
    }
    __syncthreads();   // all w3/h2 reads done before overwrite

    // ================= GRU setup =================
    unsigned* hhi  = smu;            // [128][36]
    unsigned* hlo  = smu + 4608;
    unsigned* whhh = smu + 9216;     // [192][40]
    unsigned* whhl = smu + 16896;
    float*    gh   = sm + 24576;     // [128][196]
    float*    wih  = sm + 49664;     // [192][2]
    float*    sbih = sm + 50048;
    float*    sbhh = sm + 50240;
    float*    swo  = sm + 50432;
    float*    sbo  = sm + 50560;
    float*    x    = sm + 50564;     // [128][2]
    float*    xh   = sm + 50820;     // [128][20]

    #pragma unroll
    for (int i = tid; i < 3072; i += 512) {
        int half = (i >= 1536), j = half ? i - 1536 : i;
        int n = j >> 3, q4 = (j & 7) * 4;
        cpa16((half ? whhl : whhh) + n * 40 + q4, (half ? g_Whl : g_Whh) + n * 32 + q4);
    }
    cp_commit();
    if (tid < 384) wih[tid] = Wih[tid];
    if (tid < 192) { sbih[tid] = bih[tid]; sbhh[tid] = bhh[tid]; }
    if (tid < 128) swo[tid] = Wo[tid];
    if (tid < 2)   sbo[tid] = bo[tid];
    if (tid < 256) x[tid] = 0.f;

    // GEMM3 epilogue -> packed h
    #pragma unroll
    for (int mt = 0; mt < 2; mt++) {
        #pragma unroll
        for (int nt = 0; nt < 2; nt++) {
            int m = wm * 32 + mt * 16 + g;
            int n = wn * 16 + nt * 8 + 2 * tg;
            int nu = n >> 1;
            float bv0 = __ldg(b3 + n), bv1 = __ldg(b3 + n + 1);
            unsigned hi, lo;
            split2(relu_(acc3[mt][nt][0] + bv0), relu_(acc3[mt][nt][1] + bv1), hi, lo);
            hhi[m * 36 + nu] = hi; hlo[m * 36 + nu] = lo;
            split2(relu_(acc3[mt][nt][2] + bv0), relu_(acc3[mt][nt][3] + bv1), hi, lo);
            hhi[(m + 8) * 36 + nu] = hi; hlo[(m + 8) * 36 + nu] = lo;
        }
    }
    cp_wait<0>();
    __syncthreads();

    // ================= GRU: warp-specialized pipeline =================
    // barriers: 1+hb = h[hb] ready (gates -> mma), 3+hb = gh[hb] ready (mma -> gates)
    if (wid < 8) {
        // -------- mma group: warps 0-7, 4m x 2n over each 64-row half --------
        const int wmm = wid & 3, wnn = wid >> 2;
        for (int t = 0; t < PLEN; t++) {
            #pragma unroll
            for (int hb = 0; hb < 2; hb++) {
                if (t > 0) bar_sync(1 + hb);
                float acc[12][4];
                #pragma unroll
                for (int b = 0; b < 12; b++)
                    #pragma unroll
                    for (int c = 0; c < 4; c++) acc[b][c] = 0.f;
                #pragma unroll
                for (int q = 0; q < 4; q++) {
                    int u0 = q * 8;
                    int m = hb * 64 + wmm * 16 + g;
                    unsigned Ah[4], Al[4];
                    Ah[0] = hhi[m * 36 + u0 + tg];     Ah[1] = hhi[(m + 8) * 36 + u0 + tg];
                    Ah[2] = hhi[m * 36 + u0 + tg + 4]; Ah[3] = hhi[(m + 8) * 36 + u0 + tg + 4];
                    Al[0] = hlo[m * 36 + u0 + tg];     Al[1] = hlo[(m + 8) * 36 + u0 + tg];
                    Al[2] = hlo[m * 36 + u0 + tg + 4]; Al[3] = hlo[(m + 8) * 36 + u0 + tg + 4];
                    #pragma unroll
                    for (int nt = 0; nt < 12; nt++) {
                        int nrow = wnn * 96 + nt * 8 + g;
                        uint2 B = *(const uint2*)(whhh + nrow * 40 + u0 + tg * 2);
                        uint2 C = *(const uint2*)(whhl + nrow * 40 + u0 + tg * 2);
                        mma16(acc[nt], Ah, B.x, B.y);
                        mma16(acc[nt], Ah, C.x, C.y);
                        mma16(acc[nt], Al, B.x, B.y);
                    }
                }
                #pragma unroll
                for (int nt = 0; nt < 12; nt++) {
                    int m = hb * 64 + wmm * 16 + g;
                    int n = wnn * 96 + nt * 8 + 2 * tg;
                    *(float2*)&gh[m * 196 + n]       = make_float2(acc[nt][0], acc[nt][1]);
                    *(float2*)&gh[(m + 8) * 196 + n] = make_float2(acc[nt][2], acc[nt][3]);
                }
                bar_arrive(3 + hb);
            }
        }
    } else {
        // -------- gate group: warps 8-15, 4 threads per row --------
        const int gt = tid - 256;
        const int row4 = gt >> 2, c = gt & 3;
        for (int t = 0; t < PLEN; t++) {
            #pragma unroll
            for (int hb = 0; hb < 2; hb++) {
                bar_sync(3 + hb);
                int r = hb * 64 + row4;
                float x0v = x[2 * r], x1v = x[2 * r + 1];
                float s0 = 0.f, s1 = 0.f;
                #pragma unroll
                for (int i = 0; i < 8; i++) {
                    int cc = c * 8 + i;
                    unsigned uh = hhi[r * 36 + cc], ul = hlo[r * 36 + cc];
                    float hv0 = bflo(uh) + bflo(ul);
                    float hv1 = bfhi(uh) + bfhi(ul);
                    float hn[2];
                    #pragma unroll
                    for (int e = 0; e < 2; e++) {
                        int j = 2 * cc + e;
                        float ghr = gh[r * 196 + j]       + sbhh[j];
                        float ghz = gh[r * 196 + j + 64]  + sbhh[j + 64];
                        float ghn = gh[r * 196 + j + 128] + sbhh[j + 128];
                        float gir = x0v * wih[j * 2]         + x1v * wih[j * 2 + 1]         + sbih[j];
                        float giz = x0v * wih[(j + 64) * 2]  + x1v * wih[(j + 64) * 2 + 1]  + sbih[j + 64];
                        float gin = x0v * wih[(j + 128) * 2] + x1v * wih[(j + 128) * 2 + 1] + sbih[j + 128];
                        float rg = __fdividef(1.f, 1.f + __expf(-(gir + ghr)));
                        float zg = __fdividef(1.f, 1.f + __expf(-(giz + ghz)));
                        float av = gin + rg * ghn;
                        float e2 = __expf(2.f * fabsf(av));
                        float tv = 1.f - __fdividef(2.f, e2 + 1.f);
                        float ng = copysignf(tv, av);
                        float hv = e ? hv1 : hv0;
                        hn[e] = (1.f - zg) * ng + zg * hv;
                    }
                    unsigned nhi, nlo;
                    split2(hn[0], hn[1], nhi, nlo);
                    hhi[r * 36 + cc] = nhi; hlo[r * 36 + cc] = nlo;
                    s0 += hn[0] * swo[2 * cc]      + hn[1] * swo[2 * cc + 1];
                    s1 += hn[0] * swo[64 + 2 * cc] + hn[1] * swo[64 + 2 * cc + 1];
                }
                s0 += __shfl_xor_sync(0xFFFFFFFFu, s0, 1);
                s0 += __shfl_xor_sync(0xFFFFFFFFu, s0, 2);
                s1 += __shfl_xor_sync(0xFFFFFFFFu, s1, 1);
                s1 += __shfl_xor_sync(0xFFFFFFFFu, s1, 2);
                if (c == 0) {
                    float xv0 = x0v + s0 + sbo[0];
                    float xv1 = x1v + s1 + sbo[1];
                    x[2 * r] = xv0; x[2 * r + 1] = xv1;
                    xh[r * 20 + 2 * t] = xv0; xh[r * 20 + 2 * t + 1] = xv1;
                }
                bar_arrive(1 + hb);
            }
        }
    }
    __syncthreads();

    // coalesced output: out[b, t, o]
    #pragma unroll
    for (int i = tid; i < 640; i += 512) {
        int r = i / 5, q = (i % 5) * 4;
        *(float4*)&out[(size_t)(m0 + r) * 20 + q] = *(const float4*)&xh[r * 20 + q];
    }
}

// ---------------------------------------------------------------------------
extern "C" void kernel_launch(void* const* d_in, const int* in_sizes, int n_in,
                              void* d_out, int out_size)
{
    const float* z   = (const float*)d_in[0];
    const float* W1  = (const float*)d_in[1];
    const float* b1  = (const float*)d_in[2];
    const float* W2  = (const float*)d_in[3];
    const float* b2  = (const float*)d_in[4];
    const float* W3  = (const float*)d_in[5];
    const float* b3  = (const float*)d_in[6];
    const float* Wih = (const float*)d_in[7];
    const float* Whh = (const float*)d_in[8];
    const float* bih = (const float*)d_in[9];
    const float* bhh = (const float*)d_in[10];
    const float* Wo  = (const float*)d_in[11];
    const float* bo  = (const float*)d_in[12];
    float* out = (float*)d_out;

    const int smem = 54272 * 4;  // 217088 B
    cudaFuncSetAttribute(fused_kernel, cudaFuncAttributeMaxDynamicSharedMemorySize, smem);

    prep_kernel<<<288, 256>>>(W1, W2, W3, Whh);
    fused_kernel<<<BS / 128, 512, smem>>>(z, b1, b2, b3, Wih, bih, bhh, Wo, bo, out);
}